// round 15
// baseline (speedup 1.0000x reference)
#include <cuda_runtime.h>
#include <cuda_fp16.h>
#include <cstdint>

#define TPB 416
#define T_ 200
#define D_ 64
#define H1_ 80
#define H2_ 40
#define C_ 64

// ---- smem half-index layout ----
#define KH   0            // k fp16 [208][72]; cols 64-71 zero
#define KS   72
#define WCH  14976        // Wc fp16 [64][216] (zero-filled AFTER fused GEMM)
#define WCS  216
#define MTH  14976        // M^T fp16 [80][72]   — aliases Wc, dead after fused GEMM
#define W2H  20736        // W2^T fp16 [40][88]  — aliases Wc, dead after fused GEMM
#define HS   88
// ---- float-index tail (starts at half 28800) ----
#define QA    14400
#define PA1   14480
#define PB2   14560
#define PA2   14600
#define PWF   14640
#define WGT   14680
#define PART  14880       // [72] ui numerator accumulators
#define WSF   14952       // [64] ws accumulators
#define SMEM_FLOATS 15016
#define SMEM_BYTES (SMEM_FLOATS * 4)   // 60,064 B -> 3 CTAs/SM

// ---- device-global prepped weights ----
__device__ __align__(16) __half g_w1bc[H1_ * D_];   // (W1b - W1c)^T  [h][d]
__device__ __align__(16) __half g_w1d [H1_ * D_];   // W1d^T          [h][d]
__device__ __align__(16) __half g_w1ac[H1_ * D_];   // (W1a + W1c)^T  [h][d]
__device__ __align__(16) __half g_w2t [H2_ * HS];   // W2^T padded    [j][88]

__device__ __forceinline__ void mma16816(float* c, uint32_t a0, uint32_t a1,
                                         uint32_t a2, uint32_t a3,
                                         uint32_t b0, uint32_t b1) {
    asm volatile(
        "mma.sync.aligned.m16n8k16.row.col.f32.f16.f16.f32 "
        "{%0,%1,%2,%3}, {%4,%5,%6,%7}, {%8,%9}, {%0,%1,%2,%3};"
        : "+f"(c[0]), "+f"(c[1]), "+f"(c[2]), "+f"(c[3])
        : "r"(a0), "r"(a1), "r"(a2), "r"(a3), "r"(b0), "r"(b1));
}
__device__ __forceinline__ void ldm_x4(uint32_t* r, uint32_t addr) {
    asm volatile("ldmatrix.sync.aligned.m8n8.x4.shared.b16 {%0,%1,%2,%3}, [%4];"
        : "=r"(r[0]), "=r"(r[1]), "=r"(r[2]), "=r"(r[3]) : "r"(addr));
}
__device__ __forceinline__ void ldm_x2(uint32_t* r, uint32_t addr) {
    asm volatile("ldmatrix.sync.aligned.m8n8.x2.shared.b16 {%0,%1}, [%2];"
        : "=r"(r[0]), "=r"(r[1]) : "r"(addr));
}
__device__ __forceinline__ void ldm_x4t(uint32_t* r, uint32_t addr) {
    asm volatile("ldmatrix.sync.aligned.m8n8.x4.trans.shared.b16 {%0,%1,%2,%3}, [%4];"
        : "=r"(r[0]), "=r"(r[1]), "=r"(r[2]), "=r"(r[3]) : "r"(addr));
}
__device__ __forceinline__ void ldm_x2t(uint32_t* r, uint32_t addr) {
    asm volatile("ldmatrix.sync.aligned.m8n8.x2.trans.shared.b16 {%0,%1}, [%2];"
        : "=r"(r[0]), "=r"(r[1]) : "r"(addr));
}
__device__ __forceinline__ uint32_t sptr(const void* p) {
    return (uint32_t)__cvta_generic_to_shared(p);
}
__device__ __forceinline__ uint32_t packh2(float a, float b) {
    __half2 h = __floats2half2_rn(a, b);
    return *(uint32_t*)&h;
}

// ---------- prep kernel: batch-invariant weight transforms only ----------
__global__ void prep_w(const float* __restrict__ W1, const float* __restrict__ W2) {
    const int g = blockIdx.x * blockDim.x + threadIdx.x;
    const int stride = gridDim.x * blockDim.x;
    for (int i = g; i < H1_ * D_; i += stride) {
        const int h = i >> 6, d = i & 63;
        g_w1bc[i] = __float2half_rn(W1[(64 + d) * H1_ + h] - W1[(128 + d) * H1_ + h]);
        g_w1d[i]  = __float2half_rn(W1[(192 + d) * H1_ + h]);
        g_w1ac[i] = __float2half_rn(W1[d * H1_ + h] + W1[(128 + d) * H1_ + h]);
    }
    for (int i = g; i < H2_ * HS; i += stride) {
        const int j = i / HS, c = i - j * HS;
        g_w2t[i] = (c < H1_) ? __float2half_rn(W2[c * H2_ + j]) : __float2half_rn(0.f);
    }
}

// ---------------------------- main kernel ----------------------------
__global__ __launch_bounds__(TPB, 3)
void din_kernel(const float* __restrict__ q, const float* __restrict__ k,
                const int* __restrict__ mask, const int* __restrict__ cate,
                const float* __restrict__ b1, const float* __restrict__ a1,
                const float* __restrict__ b2, const float* __restrict__ a2,
                const float* __restrict__ Wf, const float* __restrict__ bf,
                float* __restrict__ out_ui, float* __restrict__ out_ch)
{
    extern __shared__ float sm[];
    __half* sh = (__half*)sm;
    const int b = blockIdx.x;
    const int tid = threadIdx.x;
    const int lane = tid & 31, warp = tid >> 5;
    const float* qb = q + b * D_;

    // ---------------- Phase 0: params, k->fp16, W2^T, M^T, qa ----------------
    if (tid < H1_) sm[PA1 + tid] = a1[tid];
    if (tid < H2_) { sm[PB2 + tid] = b2[tid]; sm[PA2 + tid] = a2[tid]; sm[PWF + tid] = Wf[tid]; }
    if (tid < C_)  sm[WSF + tid] = 0.f;
    if (tid < 72)  sm[PART + tid] = 0.f;
    {   // k -> fp16 [208][72]
        const float4* k4 = (const float4*)(k + (size_t)b * T_ * D_);
        for (int idx = tid; idx < T_ * 16; idx += TPB) {
            float4 v = k4[idx];
            const int t = idx >> 4, f4 = idx & 15;
            uint2 u;
            *(__half2*)&u.x = __floats2half2_rn(v.x, v.y);
            *(__half2*)&u.y = __floats2half2_rn(v.z, v.w);
            *(uint2*)&sh[t * KS + f4 * 4] = u;
        }
        if (tid < 128) {                       // zero rows 200..207, cols 0..63
            const int t = 200 + (tid >> 4), d4 = (tid & 15) * 4;
            *(uint2*)&sh[t * KS + d4] = make_uint2(0u, 0u);
        }
        if (tid < 208)                         // zero cols 64..71 (all rows)
            *(uint4*)&sh[tid * KS + 64] = make_uint4(0u, 0u, 0u, 0u);
    }
    {   // W2^T pre-padded copy: 440 uint4
        const uint4* w2g = (const uint4*)g_w2t;
        uint4* w2s = (uint4*)&sh[W2H];
        for (int i = tid; i < 440; i += TPB) w2s[i] = w2g[i];
    }
    {   // M^T[h][d] = w1bc + q_d * w1d
        const __half2* bc2 = (const __half2*)g_w1bc;
        const __half2* dd2 = (const __half2*)g_w1d;
        for (int i2 = tid; i2 < H1_ * 32; i2 += TPB) {
            const int h = i2 >> 5, dp = i2 & 31;
            float2 bc = __half22float2(bc2[i2]);
            float2 dd = __half22float2(dd2[i2]);
            const float q0 = __ldg(qb + dp * 2), q1 = __ldg(qb + dp * 2 + 1);
            *(__half2*)&sh[MTH + h * KS + dp * 2] =
                __floats2half2_rn(fmaf(q0, dd.x, bc.x), fmaf(q1, dd.y, bc.y));
        }
    }
    if (tid < 320) {   // qa[h] = b1[h] + q . w1ac[h]
        const int h = tid >> 2, qq = tid & 3;
        const __half2* ac2 = (const __half2*)(g_w1ac + h * 64 + qq * 16);
        float s = 0.f;
#pragma unroll
        for (int p = 0; p < 8; ++p) {
            float2 f = __half22float2(ac2[p]);
            s += __ldg(qb + qq * 16 + 2 * p) * f.x + __ldg(qb + qq * 16 + 2 * p + 1) * f.y;
        }
        s += __shfl_xor_sync(0xffffffffu, s, 1);
        s += __shfl_xor_sync(0xffffffffu, s, 2);
        if (qq == 0) sm[QA + h] = s + b1[h];
    }
    __syncthreads();

    // ------- Fused GEMM1 -> PReLU -> GEMM2 -> logits (13 warps, reg-resident) -------
    {
        const int mt = warp;
        const int r = lane >> 2, qd = lane & 3;
        const uint32_t a_base  = sptr(&sh[(mt * 16 + (lane & 15)) * KS + ((lane >> 4) << 3)]);
        const uint32_t b1_base = sptr(&sh[MTH + (((lane >> 4) << 3) + (lane & 7)) * KS
                                              + (((lane >> 3) & 1) << 3)]);
        const uint32_t b2_base = sptr(&sh[W2H + (((lane >> 4) << 3) + (lane & 7)) * HS
                                              + (((lane >> 3) & 1) << 3)]);
        float acc2[5][4];
#pragma unroll
        for (int jn = 0; jn < 5; ++jn)
#pragma unroll
            for (int x = 0; x < 4; ++x) acc2[jn][x] = 0.f;

#pragma unroll
        for (int np = 0; np < 5; ++np) {
            float alo[4] = {0.f, 0.f, 0.f, 0.f};
            float ahi[4] = {0.f, 0.f, 0.f, 0.f};
#pragma unroll
            for (int kk = 0; kk < 4; ++kk) {
                uint32_t af[4], bp[4];
                ldm_x4(af, a_base + kk * 32);
                ldm_x4(bp, b1_base + (uint32_t)(np * 16 * KS * 2) + kk * 32);
                mma16816(alo, af[0], af[1], af[2], af[3], bp[0], bp[1]);
                mma16816(ahi, af[0], af[1], af[2], af[3], bp[2], bp[3]);
            }
            const int jl = np * 16 + qd * 2, jh = jl + 8;
            const float ql0 = sm[QA + jl],  ql1 = sm[QA + jl + 1];
            const float ll0 = sm[PA1 + jl], ll1 = sm[PA1 + jl + 1];
            const float qh0 = sm[QA + jh],  qh1 = sm[QA + jh + 1];
            const float lh0 = sm[PA1 + jh], lh1 = sm[PA1 + jh + 1];
            float v0 = alo[0] + ql0; v0 = (v0 > 0.f) ? v0 : v0 * ll0;
            float v1 = alo[1] + ql1; v1 = (v1 > 0.f) ? v1 : v1 * ll1;
            float v2 = alo[2] + ql0; v2 = (v2 > 0.f) ? v2 : v2 * ll0;
            float v3 = alo[3] + ql1; v3 = (v3 > 0.f) ? v3 : v3 * ll1;
            float w0 = ahi[0] + qh0; w0 = (w0 > 0.f) ? w0 : w0 * lh0;
            float w1 = ahi[1] + qh1; w1 = (w1 > 0.f) ? w1 : w1 * lh1;
            float w2 = ahi[2] + qh0; w2 = (w2 > 0.f) ? w2 : w2 * lh0;
            float w3 = ahi[3] + qh1; w3 = (w3 > 0.f) ? w3 : w3 * lh1;
            const uint32_t A0 = packh2(v0, v1);
            const uint32_t A1 = packh2(v2, v3);
            const uint32_t A2 = packh2(w0, w1);
            const uint32_t A3 = packh2(w2, w3);
            uint32_t b01[4], b23[4], b4[2];
            const uint32_t bb = b2_base + np * 32;
            ldm_x4(b01, bb);
            ldm_x4(b23, bb + 2u * 8 * HS * 2);
            ldm_x2(b4,  bb + 4u * 8 * HS * 2);
            mma16816(acc2[0], A0, A1, A2, A3, b01[0], b01[1]);
            mma16816(acc2[1], A0, A1, A2, A3, b01[2], b01[3]);
            mma16816(acc2[2], A0, A1, A2, A3, b23[0], b23[1]);
            mma16816(acc2[3], A0, A1, A2, A3, b23[2], b23[3]);
            mma16816(acc2[4], A0, A1, A2, A3, b4[0],  b4[1]);
        }
        float slo = 0.f, shi = 0.f;
#pragma unroll
        for (int jn = 0; jn < 5; ++jn) {
            const int j = jn * 8 + qd * 2;
            const float bb0 = sm[PB2 + j], bb1 = sm[PB2 + j + 1];
            const float al0 = sm[PA2 + j], al1 = sm[PA2 + j + 1];
            const float wf0 = sm[PWF + j], wf1 = sm[PWF + j + 1];
            float x0 = acc2[jn][0] + bb0; x0 = (x0 > 0.f) ? x0 : x0 * al0;
            float x1 = acc2[jn][1] + bb1; x1 = (x1 > 0.f) ? x1 : x1 * al1;
            float x2 = acc2[jn][2] + bb0; x2 = (x2 > 0.f) ? x2 : x2 * al0;
            float x3 = acc2[jn][3] + bb1; x3 = (x3 > 0.f) ? x3 : x3 * al1;
            slo += x0 * wf0 + x1 * wf1;
            shi += x2 * wf0 + x3 * wf1;
        }
        slo += __shfl_xor_sync(0xffffffffu, slo, 1);
        slo += __shfl_xor_sync(0xffffffffu, slo, 2);
        shi += __shfl_xor_sync(0xffffffffu, shi, 1);
        shi += __shfl_xor_sync(0xffffffffu, shi, 2);
        if (qd == 0) {
            const float bff = bf[0];
            const int t0 = mt * 16 + r, t1 = t0 + 8;
            if (t0 < T_) {
                float s = slo + bff;
                if (mask[b * T_ + t0] == 0) s = -4294967295.0f;
                sm[WGT + t0] = s * 0.125f;
            }
            if (t1 < T_) {
                float s = shi + bff;
                if (mask[b * T_ + t1] == 0) s = -4294967295.0f;
                sm[WGT + t1] = s * 0.125f;
            }
        }
    }
    __syncthreads();

    // ------- Softmax (warp-redundant) + zero Wc (MTH/W2H now dead) -------
    float wreg = 0.f;
    {
        float mx = -3.4e38f, sv = 0.f;
        float vals[7];
#pragma unroll
        for (int j = 0; j < 7; ++j) {
            const int t = lane + 32 * j;
            vals[j] = (t < T_) ? sm[WGT + t] : -3.4e38f;
            mx = fmaxf(mx, vals[j]);
        }
#pragma unroll
        for (int o = 16; o; o >>= 1) mx = fmaxf(mx, __shfl_xor_sync(0xffffffffu, mx, o));
#pragma unroll
        for (int j = 0; j < 7; ++j)
            sv += (lane + 32 * j < T_) ? __expf(vals[j] - mx) : 0.f;
#pragma unroll
        for (int o = 16; o; o >>= 1) sv += __shfl_xor_sync(0xffffffffu, sv, o);
        if (tid < T_) wreg = __expf(sm[WGT + tid] - mx) / sv;
    }
    {   // zero Wc [64][216] fp16 = 1728 uint4
        uint4* wc4 = (uint4*)&sh[WCH];
        for (int i = tid; i < (C_ * WCS) / 8; i += TPB) wc4[i] = make_uint4(0u, 0u, 0u, 0u);
    }
    __syncthreads();

    // ------- Scatter w into Wc + ws accumulation (fp16-rounded w for both) -------
    if (tid < T_) {
        const __half wh = __float2half_rn(wreg);
        const int ct = cate[b * T_ + tid];
        sh[WCH + ct * WCS + tid] = wh;
        atomicAdd(&sm[WSF + ct], __half2float(wh));
    }
    __syncthreads();

    // ------- Cate GEMM (HMMA): num = Wc @ k; normalize in-reg; ui partials -------
    if (warp < 12) {
        const int mt = warp & 3, g = warp >> 2;
        const int r = lane >> 2, qd = lane & 3;
        const int n0 = g * 24;
        const uint32_t aw_base = sptr(&sh[WCH + (mt * 16 + (lane & 15)) * WCS
                                              + ((lane >> 4) << 3)]);
        const int krow = (lane & 7) + ((lane >> 3) & 1) * 8;
        const uint32_t bt4_base = sptr(&sh[krow * KS + n0 + ((lane >> 4) << 3)]);
        const uint32_t bt2_base = sptr(&sh[krow * KS + n0 + 16]);
        float acc[3][4];
#pragma unroll
        for (int j = 0; j < 3; ++j)
#pragma unroll
            for (int x = 0; x < 4; ++x) acc[j][x] = 0.f;
#pragma unroll
        for (int kc = 0; kc < 13; ++kc) {
            uint32_t af[4], bt[4], b2r[2];
            ldm_x4 (af,  aw_base  + kc * 32);
            ldm_x4t(bt,  bt4_base + (uint32_t)(kc * 16 * KS * 2));
            ldm_x2t(b2r, bt2_base + (uint32_t)(kc * 16 * KS * 2));
            mma16816(acc[0], af[0], af[1], af[2], af[3], bt[0], bt[1]);
            mma16816(acc[1], af[0], af[1], af[2], af[3], bt[2], bt[3]);
            mma16816(acc[2], af[0], af[1], af[2], af[3], b2r[0], b2r[1]);
        }
        const int c0 = mt * 16 + r;
        const float inv0 = 1.0f / (sm[WSF + c0] + 1e-10f);
        const float inv1 = 1.0f / (sm[WSF + c0 + 8] + 1e-10f);
        float* ch = out_ch + (size_t)b * C_ * D_;
#pragma unroll
        for (int j = 0; j < 3; ++j) {
            const int col = n0 + j * 8 + qd * 2;
            if (col < 64) {       // uniform per (g,j): g==2,j==2 skipped entirely
                *(float2*)&ch[c0 * D_ + col] =
                    make_float2(acc[j][0] * inv0, acc[j][1] * inv0);
                *(float2*)&ch[(c0 + 8) * D_ + col] =
                    make_float2(acc[j][2] * inv1, acc[j][3] * inv1);
                float s0 = acc[j][0] + acc[j][2];
                float s1 = acc[j][1] + acc[j][3];
#pragma unroll
                for (int o = 4; o <= 16; o <<= 1) {   // reduce over r
                    s0 += __shfl_xor_sync(0xffffffffu, s0, o);
                    s1 += __shfl_xor_sync(0xffffffffu, s1, o);
                }
                if (r == 0) {
                    atomicAdd(&sm[PART + col], s0);
                    atomicAdd(&sm[PART + col + 1], s1);
                }
            }
        }
    }
    __syncthreads();

    // ------- ui[d] = sum_c numerator[c][d] -------
    if (tid < D_) out_ui[b * D_ + tid] = sm[PART + tid];
}

extern "C" void kernel_launch(void* const* d_in, const int* in_sizes, int n_in,
                              void* d_out, int out_size)
{
    const float* q    = (const float*)d_in[0];
    const float* k    = (const float*)d_in[1];
    const int*   mask = (const int*)d_in[2];
    const int*   cate = (const int*)d_in[3];
    // d_in[4] = cate_count (compile-time C_=64)
    const float* W1 = (const float*)d_in[5];
    const float* b1 = (const float*)d_in[6];
    const float* a1 = (const float*)d_in[7];
    const float* W2 = (const float*)d_in[8];
    const float* b2 = (const float*)d_in[9];
    const float* a2 = (const float*)d_in[10];
    const float* Wf = (const float*)d_in[11];
    const float* bf = (const float*)d_in[12];

    const int B = in_sizes[0] / D_;
    float* out_ui = (float*)d_out;                     // [B, 64]
    float* out_ch = (float*)d_out + (size_t)B * D_;    // [B, 64, 64]

    prep_w<<<8, 256>>>(W1, W2);

    cudaFuncSetAttribute(din_kernel, cudaFuncAttributeMaxDynamicSharedMemorySize, SMEM_BYTES);
    din_kernel<<<B, TPB, SMEM_BYTES>>>(q, k, mask, cate, b1, a1, b2, a2, Wf, bf,
                                       out_ui, out_ch);
}

// round 16
// speedup vs baseline: 1.0025x; 1.0025x over previous
#include <cuda_runtime.h>
#include <cuda_fp16.h>
#include <cstdint>

#define TPB 416
#define T_ 200
#define D_ 64
#define H1_ 80
#define H2_ 40
#define C_ 64

// ---- smem half-index layout ----
#define KH   0            // k fp16 [208][72]; cols 64-71 zero
#define KS   72
#define WCH  14976        // Wc fp16 [64][216] (zero-filled AFTER fused GEMM)
#define WCS  216
#define MTH  14976        // M^T fp16 [80][72]   — aliases Wc, dead after fused GEMM
#define W2H  20736        // W2^T fp16 [40][88]  — aliases Wc, dead after fused GEMM
#define HS   88
// ---- float-index tail (starts at half 28800) ----
#define QA    14400
#define PA1   14480
#define PB2   14560
#define PA2   14600
#define PWF   14640
#define WGT   14680
#define PART  14880       // [72] ui numerator accumulators
#define WSF   14952       // [64] ws accumulators
#define SMEM_FLOATS 15016
#define SMEM_BYTES (SMEM_FLOATS * 4)   // 60,064 B -> 3 CTAs/SM

// ---- device-global prepped weights ----
__device__ __align__(16) __half g_w1bc[H1_ * D_];   // (W1b - W1c)^T  [h][d]
__device__ __align__(16) __half g_w1d [H1_ * D_];   // W1d^T          [h][d]
__device__ __align__(16) __half g_w1ac[H1_ * D_];   // (W1a + W1c)^T  [h][d]
__device__ __align__(16) __half g_w2t [H2_ * HS];   // W2^T padded    [j][88]

__device__ __forceinline__ void mma16816(float* c, uint32_t a0, uint32_t a1,
                                         uint32_t a2, uint32_t a3,
                                         uint32_t b0, uint32_t b1) {
    asm volatile(
        "mma.sync.aligned.m16n8k16.row.col.f32.f16.f16.f32 "
        "{%0,%1,%2,%3}, {%4,%5,%6,%7}, {%8,%9}, {%0,%1,%2,%3};"
        : "+f"(c[0]), "+f"(c[1]), "+f"(c[2]), "+f"(c[3])
        : "r"(a0), "r"(a1), "r"(a2), "r"(a3), "r"(b0), "r"(b1));
}
__device__ __forceinline__ void ldm_x4(uint32_t* r, uint32_t addr) {
    asm volatile("ldmatrix.sync.aligned.m8n8.x4.shared.b16 {%0,%1,%2,%3}, [%4];"
        : "=r"(r[0]), "=r"(r[1]), "=r"(r[2]), "=r"(r[3]) : "r"(addr));
}
__device__ __forceinline__ void ldm_x2(uint32_t* r, uint32_t addr) {
    asm volatile("ldmatrix.sync.aligned.m8n8.x2.shared.b16 {%0,%1}, [%2];"
        : "=r"(r[0]), "=r"(r[1]) : "r"(addr));
}
__device__ __forceinline__ void ldm_x4t(uint32_t* r, uint32_t addr) {
    asm volatile("ldmatrix.sync.aligned.m8n8.x4.trans.shared.b16 {%0,%1,%2,%3}, [%4];"
        : "=r"(r[0]), "=r"(r[1]), "=r"(r[2]), "=r"(r[3]) : "r"(addr));
}
__device__ __forceinline__ void ldm_x2t(uint32_t* r, uint32_t addr) {
    asm volatile("ldmatrix.sync.aligned.m8n8.x2.trans.shared.b16 {%0,%1}, [%2];"
        : "=r"(r[0]), "=r"(r[1]) : "r"(addr));
}
__device__ __forceinline__ uint32_t sptr(const void* p) {
    return (uint32_t)__cvta_generic_to_shared(p);
}
__device__ __forceinline__ uint32_t packh2(float a, float b) {
    __half2 h = __floats2half2_rn(a, b);
    return *(uint32_t*)&h;
}

// ---------- prep kernel: batch-invariant weight transforms only ----------
__global__ void prep_w(const float* __restrict__ W1, const float* __restrict__ W2) {
    const int g = blockIdx.x * blockDim.x + threadIdx.x;
    const int stride = gridDim.x * blockDim.x;
    for (int i = g; i < H1_ * D_; i += stride) {
        const int h = i >> 6, d = i & 63;
        g_w1bc[i] = __float2half_rn(W1[(64 + d) * H1_ + h] - W1[(128 + d) * H1_ + h]);
        g_w1d[i]  = __float2half_rn(W1[(192 + d) * H1_ + h]);
        g_w1ac[i] = __float2half_rn(W1[d * H1_ + h] + W1[(128 + d) * H1_ + h]);
    }
    for (int i = g; i < H2_ * HS; i += stride) {
        const int j = i / HS, c = i - j * HS;
        g_w2t[i] = (c < H1_) ? __float2half_rn(W2[c * H2_ + j]) : __float2half_rn(0.f);
    }
}

// ---------------------------- main kernel ----------------------------
__global__ __launch_bounds__(TPB, 3)
void din_kernel(const float* __restrict__ q, const float* __restrict__ k,
                const int* __restrict__ mask, const int* __restrict__ cate,
                const float* __restrict__ b1, const float* __restrict__ a1,
                const float* __restrict__ b2, const float* __restrict__ a2,
                const float* __restrict__ Wf, const float* __restrict__ bf,
                float* __restrict__ out_ui, float* __restrict__ out_ch)
{
    extern __shared__ float sm[];
    __half* sh = (__half*)sm;
    const int b = blockIdx.x;
    const int tid = threadIdx.x;
    const int lane = tid & 31, warp = tid >> 5;
    const float* qb = q + b * D_;

    // ---------------- Phase 0: params, k->fp16, W2^T, M^T, qa ----------------
    if (tid < H1_) sm[PA1 + tid] = a1[tid];
    if (tid < H2_) { sm[PB2 + tid] = b2[tid]; sm[PA2 + tid] = a2[tid]; sm[PWF + tid] = Wf[tid]; }
    if (tid < C_)  sm[WSF + tid] = 0.f;
    if (tid < 72)  sm[PART + tid] = 0.f;
    {   // k -> fp16 [208][72]
        const float4* k4 = (const float4*)(k + (size_t)b * T_ * D_);
        for (int idx = tid; idx < T_ * 16; idx += TPB) {
            float4 v = k4[idx];
            const int t = idx >> 4, f4 = idx & 15;
            uint2 u;
            *(__half2*)&u.x = __floats2half2_rn(v.x, v.y);
            *(__half2*)&u.y = __floats2half2_rn(v.z, v.w);
            *(uint2*)&sh[t * KS + f4 * 4] = u;
        }
        if (tid < 128) {                       // zero rows 200..207, cols 0..63
            const int t = 200 + (tid >> 4), d4 = (tid & 15) * 4;
            *(uint2*)&sh[t * KS + d4] = make_uint2(0u, 0u);
        }
        if (tid < 208)                         // zero cols 64..71 (all rows)
            *(uint4*)&sh[tid * KS + 64] = make_uint4(0u, 0u, 0u, 0u);
    }
    {   // W2^T pre-padded copy: 440 uint4
        const uint4* w2g = (const uint4*)g_w2t;
        uint4* w2s = (uint4*)&sh[W2H];
        for (int i = tid; i < 440; i += TPB) w2s[i] = w2g[i];
    }
    {   // M^T[h][d] = w1bc + q_d * w1d
        const __half2* bc2 = (const __half2*)g_w1bc;
        const __half2* dd2 = (const __half2*)g_w1d;
        for (int i2 = tid; i2 < H1_ * 32; i2 += TPB) {
            const int h = i2 >> 5, dp = i2 & 31;
            float2 bc = __half22float2(bc2[i2]);
            float2 dd = __half22float2(dd2[i2]);
            const float q0 = __ldg(qb + dp * 2), q1 = __ldg(qb + dp * 2 + 1);
            *(__half2*)&sh[MTH + h * KS + dp * 2] =
                __floats2half2_rn(fmaf(q0, dd.x, bc.x), fmaf(q1, dd.y, bc.y));
        }
    }
    if (tid < 320) {   // qa[h] = b1[h] + q . w1ac[h]
        const int h = tid >> 2, qq = tid & 3;
        const __half2* ac2 = (const __half2*)(g_w1ac + h * 64 + qq * 16);
        float s = 0.f;
#pragma unroll
        for (int p = 0; p < 8; ++p) {
            float2 f = __half22float2(ac2[p]);
            s += __ldg(qb + qq * 16 + 2 * p) * f.x + __ldg(qb + qq * 16 + 2 * p + 1) * f.y;
        }
        s += __shfl_xor_sync(0xffffffffu, s, 1);
        s += __shfl_xor_sync(0xffffffffu, s, 2);
        if (qq == 0) sm[QA + h] = s + b1[h];
    }
    __syncthreads();

    // ------- Fused GEMM1 -> PReLU -> GEMM2 -> logits (13 warps, reg-resident) -------
    {
        const int mt = warp;
        const int r = lane >> 2, qd = lane & 3;
        const uint32_t a_base  = sptr(&sh[(mt * 16 + (lane & 15)) * KS + ((lane >> 4) << 3)]);
        const uint32_t b1_base = sptr(&sh[MTH + (((lane >> 4) << 3) + (lane & 7)) * KS
                                              + (((lane >> 3) & 1) << 3)]);
        const uint32_t b2_base = sptr(&sh[W2H + (((lane >> 4) << 3) + (lane & 7)) * HS
                                              + (((lane >> 3) & 1) << 3)]);
        float acc2[5][4];
#pragma unroll
        for (int jn = 0; jn < 5; ++jn)
#pragma unroll
            for (int x = 0; x < 4; ++x) acc2[jn][x] = 0.f;

#pragma unroll
        for (int np = 0; np < 5; ++np) {
            float alo[4] = {0.f, 0.f, 0.f, 0.f};
            float ahi[4] = {0.f, 0.f, 0.f, 0.f};
#pragma unroll
            for (int kk = 0; kk < 4; ++kk) {
                uint32_t af[4], bp[4];
                ldm_x4(af, a_base + kk * 32);
                ldm_x4(bp, b1_base + (uint32_t)(np * 16 * KS * 2) + kk * 32);
                mma16816(alo, af[0], af[1], af[2], af[3], bp[0], bp[1]);
                mma16816(ahi, af[0], af[1], af[2], af[3], bp[2], bp[3]);
            }
            const int jl = np * 16 + qd * 2, jh = jl + 8;
            const float ql0 = sm[QA + jl],  ql1 = sm[QA + jl + 1];
            const float ll0 = sm[PA1 + jl], ll1 = sm[PA1 + jl + 1];
            const float qh0 = sm[QA + jh],  qh1 = sm[QA + jh + 1];
            const float lh0 = sm[PA1 + jh], lh1 = sm[PA1 + jh + 1];
            float v0 = alo[0] + ql0; v0 = (v0 > 0.f) ? v0 : v0 * ll0;
            float v1 = alo[1] + ql1; v1 = (v1 > 0.f) ? v1 : v1 * ll1;
            float v2 = alo[2] + ql0; v2 = (v2 > 0.f) ? v2 : v2 * ll0;
            float v3 = alo[3] + ql1; v3 = (v3 > 0.f) ? v3 : v3 * ll1;
            float w0 = ahi[0] + qh0; w0 = (w0 > 0.f) ? w0 : w0 * lh0;
            float w1 = ahi[1] + qh1; w1 = (w1 > 0.f) ? w1 : w1 * lh1;
            float w2 = ahi[2] + qh0; w2 = (w2 > 0.f) ? w2 : w2 * lh0;
            float w3 = ahi[3] + qh1; w3 = (w3 > 0.f) ? w3 : w3 * lh1;
            const uint32_t A0 = packh2(v0, v1);
            const uint32_t A1 = packh2(v2, v3);
            const uint32_t A2 = packh2(w0, w1);
            const uint32_t A3 = packh2(w2, w3);
            uint32_t b01[4], b23[4], b4[2];
            const uint32_t bb = b2_base + np * 32;
            ldm_x4(b01, bb);
            ldm_x4(b23, bb + 2u * 8 * HS * 2);
            ldm_x2(b4,  bb + 4u * 8 * HS * 2);
            mma16816(acc2[0], A0, A1, A2, A3, b01[0], b01[1]);
            mma16816(acc2[1], A0, A1, A2, A3, b01[2], b01[3]);
            mma16816(acc2[2], A0, A1, A2, A3, b23[0], b23[1]);
            mma16816(acc2[3], A0, A1, A2, A3, b23[2], b23[3]);
            mma16816(acc2[4], A0, A1, A2, A3, b4[0],  b4[1]);
        }
        float slo = 0.f, shi = 0.f;
#pragma unroll
        for (int jn = 0; jn < 5; ++jn) {
            const int j = jn * 8 + qd * 2;
            const float bb0 = sm[PB2 + j], bb1 = sm[PB2 + j + 1];
            const float al0 = sm[PA2 + j], al1 = sm[PA2 + j + 1];
            const float wf0 = sm[PWF + j], wf1 = sm[PWF + j + 1];
            float x0 = acc2[jn][0] + bb0; x0 = (x0 > 0.f) ? x0 : x0 * al0;
            float x1 = acc2[jn][1] + bb1; x1 = (x1 > 0.f) ? x1 : x1 * al1;
            float x2 = acc2[jn][2] + bb0; x2 = (x2 > 0.f) ? x2 : x2 * al0;
            float x3 = acc2[jn][3] + bb1; x3 = (x3 > 0.f) ? x3 : x3 * al1;
            slo += x0 * wf0 + x1 * wf1;
            shi += x2 * wf0 + x3 * wf1;
        }
        slo += __shfl_xor_sync(0xffffffffu, slo, 1);
        slo += __shfl_xor_sync(0xffffffffu, slo, 2);
        shi += __shfl_xor_sync(0xffffffffu, shi, 1);
        shi += __shfl_xor_sync(0xffffffffu, shi, 2);
        if (qd == 0) {
            const float bff = bf[0];
            const int t0 = mt * 16 + r, t1 = t0 + 8;
            if (t0 < T_) {
                float s = slo + bff;
                if (mask[b * T_ + t0] == 0) s = -4294967295.0f;
                sm[WGT + t0] = s * 0.125f;
            }
            if (t1 < T_) {
                float s = shi + bff;
                if (mask[b * T_ + t1] == 0) s = -4294967295.0f;
                sm[WGT + t1] = s * 0.125f;
            }
        }
    }
    __syncthreads();

    // ------- Softmax (warp-redundant) + zero Wc (MTH/W2H now dead) -------
    float wreg = 0.f;
    {
        float mx = -3.4e38f, sv = 0.f;
        float vals[7];
#pragma unroll
        for (int j = 0; j < 7; ++j) {
            const int t = lane + 32 * j;
            vals[j] = (t < T_) ? sm[WGT + t] : -3.4e38f;
            mx = fmaxf(mx, vals[j]);
        }
#pragma unroll
        for (int o = 16; o; o >>= 1) mx = fmaxf(mx, __shfl_xor_sync(0xffffffffu, mx, o));
#pragma unroll
        for (int j = 0; j < 7; ++j)
            sv += (lane + 32 * j < T_) ? __expf(vals[j] - mx) : 0.f;
#pragma unroll
        for (int o = 16; o; o >>= 1) sv += __shfl_xor_sync(0xffffffffu, sv, o);
        if (tid < T_) wreg = __expf(sm[WGT + tid] - mx) / sv;
    }
    {   // zero Wc [64][216] fp16 = 1728 uint4
        uint4* wc4 = (uint4*)&sh[WCH];
        for (int i = tid; i < (C_ * WCS) / 8; i += TPB) wc4[i] = make_uint4(0u, 0u, 0u, 0u);
    }
    __syncthreads();

    // ------- Scatter w into Wc + ws accumulation (fp16-rounded w for both) -------
    if (tid < T_) {
        const __half wh = __float2half_rn(wreg);
        const int ct = cate[b * T_ + tid];
        sh[WCH + ct * WCS + tid] = wh;
        atomicAdd(&sm[WSF + ct], __half2float(wh));
    }
    __syncthreads();

    // ------- Cate GEMM (HMMA): num = Wc @ k; normalize in-reg; ui partials -------
    if (warp < 12) {
        const int mt = warp & 3, g = warp >> 2;
        const int r = lane >> 2, qd = lane & 3;
        const int n0 = g * 24;
        const uint32_t aw_base = sptr(&sh[WCH + (mt * 16 + (lane & 15)) * WCS
                                              + ((lane >> 4) << 3)]);
        const int krow = (lane & 7) + ((lane >> 3) & 1) * 8;
        const uint32_t bt4_base = sptr(&sh[krow * KS + n0 + ((lane >> 4) << 3)]);
        const uint32_t bt2_base = sptr(&sh[krow * KS + n0 + 16]);
        float acc[3][4];
#pragma unroll
        for (int j = 0; j < 3; ++j)
#pragma unroll
            for (int x = 0; x < 4; ++x) acc[j][x] = 0.f;
#pragma unroll
        for (int kc = 0; kc < 13; ++kc) {
            uint32_t af[4], bt[4], b2r[2];
            ldm_x4 (af,  aw_base  + kc * 32);
            ldm_x4t(bt,  bt4_base + (uint32_t)(kc * 16 * KS * 2));
            ldm_x2t(b2r, bt2_base + (uint32_t)(kc * 16 * KS * 2));
            mma16816(acc[0], af[0], af[1], af[2], af[3], bt[0], bt[1]);
            mma16816(acc[1], af[0], af[1], af[2], af[3], bt[2], bt[3]);
            mma16816(acc[2], af[0], af[1], af[2], af[3], b2r[0], b2r[1]);
        }
        const int c0 = mt * 16 + r;
        const float inv0 = 1.0f / (sm[WSF + c0] + 1e-10f);
        const float inv1 = 1.0f / (sm[WSF + c0 + 8] + 1e-10f);
        float* ch = out_ch + (size_t)b * C_ * D_;
#pragma unroll
        for (int j = 0; j < 3; ++j) {
            const int col = n0 + j * 8 + qd * 2;
            if (col < 64) {       // uniform per (g,j): g==2,j==2 skipped entirely
                *(float2*)&ch[c0 * D_ + col] =
                    make_float2(acc[j][0] * inv0, acc[j][1] * inv0);
                *(float2*)&ch[(c0 + 8) * D_ + col] =
                    make_float2(acc[j][2] * inv1, acc[j][3] * inv1);
                float s0 = acc[j][0] + acc[j][2];
                float s1 = acc[j][1] + acc[j][3];
#pragma unroll
                for (int o = 4; o <= 16; o <<= 1) {   // reduce over r
                    s0 += __shfl_xor_sync(0xffffffffu, s0, o);
                    s1 += __shfl_xor_sync(0xffffffffu, s1, o);
                }
                if (r == 0) {
                    atomicAdd(&sm[PART + col], s0);
                    atomicAdd(&sm[PART + col + 1], s1);
                }
            }
        }
    }
    __syncthreads();

    // ------- ui[d] = sum_c numerator[c][d] -------
    if (tid < D_) out_ui[b * D_ + tid] = sm[PART + tid];
}

extern "C" void kernel_launch(void* const* d_in, const int* in_sizes, int n_in,
                              void* d_out, int out_size)
{
    const float* q    = (const float*)d_in[0];
    const float* k    = (const float*)d_in[1];
    const int*   mask = (const int*)d_in[2];
    const int*   cate = (const int*)d_in[3];
    // d_in[4] = cate_count (compile-time C_=64)
    const float* W1 = (const float*)d_in[5];
    const float* b1 = (const float*)d_in[6];
    const float* a1 = (const float*)d_in[7];
    const float* W2 = (const float*)d_in[8];
    const float* b2 = (const float*)d_in[9];
    const float* a2 = (const float*)d_in[10];
    const float* Wf = (const float*)d_in[11];
    const float* bf = (const float*)d_in[12];

    const int B = in_sizes[0] / D_;
    float* out_ui = (float*)d_out;                     // [B, 64]
    float* out_ch = (float*)d_out + (size_t)B * D_;    // [B, 64, 64]

    prep_w<<<8, 256>>>(W1, W2);

    cudaFuncSetAttribute(din_kernel, cudaFuncAttributeMaxDynamicSharedMemorySize, SMEM_BYTES);
    din_kernel<<<B, TPB, SMEM_BYTES>>>(q, k, mask, cate, b1, a1, b2, a2, Wf, bf,
                                       out_ui, out_ch);
}